// round 5
// baseline (speedup 1.0000x reference)
#include <cuda_runtime.h>
#include <cuda_bf16.h>
#include <cstdint>

// Problem constants
#define BB 4
#define SS 2048
#define DD 512
#define HH 8
#define DK 64
#define DV 64
#define BS (BB * SS)          // 8192 rows total
#define QT2 64                // query rows per attention block
#define NQT2 (SS / QT2)       // 32 q-tiles per batch

// Scratch (device globals: no allocations allowed)
__device__ float g_q[BS * DK];       // pre-scaled by 0.125, tf32-rounded
__device__ float g_k[BS * DK];       // tf32-rounded
__device__ float g_v[BS * DV];       // tf32-rounded
__device__ float g_o[BS * DV];       // tf32-rounded
__device__ float g_woeff[DV * DD];   // 64 x 512, tf32-rounded

// ---------------------------------------------------------------------------
// tf32 mma helpers
// ---------------------------------------------------------------------------
__device__ __forceinline__ float f2tff(float f) {
    unsigned u;
    asm("cvt.rna.tf32.f32 %0, %1;" : "=r"(u) : "f"(f));
    return __uint_as_float(u);
}
// D(16x8,f32) += A(16x8,tf32,row) * B(8x8,tf32,col)
__device__ __forceinline__ void mma8(float* c, unsigned a0, unsigned a1,
                                     unsigned a2, unsigned a3,
                                     unsigned b0, unsigned b1) {
    asm volatile(
        "mma.sync.aligned.m16n8k8.row.col.f32.tf32.tf32.f32 "
        "{%0,%1,%2,%3}, {%4,%5,%6,%7}, {%8,%9}, {%0,%1,%2,%3};\n"
        : "+f"(c[0]), "+f"(c[1]), "+f"(c[2]), "+f"(c[3])
        : "r"(a0), "r"(a1), "r"(a2), "r"(a3), "r"(b0), "r"(b1));
}

// ---------------------------------------------------------------------------
// Kernel 1: fold Wo over identical heads: woeff[r,c] = sum_h Wo[h*64+r, c]
// (tf32-rounded so outgemm can load raw)
// ---------------------------------------------------------------------------
__global__ void woeff_kernel(const float* __restrict__ Wo) {
    int idx = blockIdx.x * blockDim.x + threadIdx.x;   // 64*512 = 32768
    if (idx < DV * DD) {
        int r = idx >> 9;
        int c = idx & 511;
        float s = 0.f;
#pragma unroll
        for (int h = 0; h < HH; ++h) s += Wo[((h << 6) + r) * DD + c];
        g_woeff[idx] = f2tff(s);
    }
}

// ---------------------------------------------------------------------------
// Kernel 2: fused projections on tf32 tensor cores.
// blockIdx.y: 0 -> q = (query@Wq+bq)*0.125 ; 1 -> k = key@Wk+bk AND v = key@Wv+bv
// Outputs are tf32-rounded (attention consumes them raw).
// 128 threads = 4 warps; warp w owns rows 16w..16w+15, all 64 cols.
// ---------------------------------------------------------------------------
__global__ void __launch_bounds__(128) proj_mma_kernel(
    const float* __restrict__ query, const float* __restrict__ key,
    const float* __restrict__ Wq, const float* __restrict__ bq,
    const float* __restrict__ Wk, const float* __restrict__ bk,
    const float* __restrict__ Wv, const float* __restrict__ bv)
{
    const int fused = blockIdx.y;           // 0: q, 1: k+v
    const float* A  = fused ? key : query;
    const int m0 = blockIdx.x * 64;

    __shared__ float As[64][36];    // A tile [row][k], pitch 36 -> bank 4g+t4
    __shared__ float W1s[32][72];   // W tile [k][n], pitch 72 -> bank 8t4+g
    __shared__ float W2s[32][72];

    const int t    = threadIdx.x;
    const int w    = t >> 5;
    const int lane = t & 31;
    const int g    = lane >> 2;
    const int t4   = lane & 3;

    float c1[8][4] = {};
    float c2[8][4] = {};

    for (int kk = 0; kk < DD; kk += 32) {
        __syncthreads();
#pragma unroll
        for (int u = 0; u < 4; ++u) {
            int fi = t + u * 128;
            int r  = fi >> 3;
            int c4 = (fi & 7) << 2;
            float4 a4 = *(const float4*)(A + (size_t)(m0 + r) * DD + kk + c4);
            As[r][c4 + 0] = f2tff(a4.x);
            As[r][c4 + 1] = f2tff(a4.y);
            As[r][c4 + 2] = f2tff(a4.z);
            As[r][c4 + 3] = f2tff(a4.w);
        }
#pragma unroll
        for (int u = 0; u < 4; ++u) {
            int fi = t + u * 128;
            int r  = fi >> 4;
            int c4 = (fi & 15) << 2;
            const float* Wa = fused ? Wk : Wq;
            float4 w4 = *(const float4*)(Wa + (size_t)(kk + r) * DK + c4);
            W1s[r][c4 + 0] = f2tff(w4.x);
            W1s[r][c4 + 1] = f2tff(w4.y);
            W1s[r][c4 + 2] = f2tff(w4.z);
            W1s[r][c4 + 3] = f2tff(w4.w);
            if (fused) {
                float4 v4 = *(const float4*)(Wv + (size_t)(kk + r) * DK + c4);
                W2s[r][c4 + 0] = f2tff(v4.x);
                W2s[r][c4 + 1] = f2tff(v4.y);
                W2s[r][c4 + 2] = f2tff(v4.z);
                W2s[r][c4 + 3] = f2tff(v4.w);
            }
        }
        __syncthreads();

#pragma unroll
        for (int kt = 0; kt < 4; ++kt) {
            unsigned a0 = __float_as_uint(As[w * 16 + g    ][kt * 8 + t4    ]);
            unsigned a1 = __float_as_uint(As[w * 16 + g + 8][kt * 8 + t4    ]);
            unsigned a2 = __float_as_uint(As[w * 16 + g    ][kt * 8 + t4 + 4]);
            unsigned a3 = __float_as_uint(As[w * 16 + g + 8][kt * 8 + t4 + 4]);
#pragma unroll
            for (int nt = 0; nt < 8; ++nt) {
                unsigned b0 = __float_as_uint(W1s[kt * 8 + t4    ][nt * 8 + g]);
                unsigned b1 = __float_as_uint(W1s[kt * 8 + t4 + 4][nt * 8 + g]);
                mma8(c1[nt], a0, a1, a2, a3, b0, b1);
            }
            if (fused) {
#pragma unroll
                for (int nt = 0; nt < 8; ++nt) {
                    unsigned b0 = __float_as_uint(W2s[kt * 8 + t4    ][nt * 8 + g]);
                    unsigned b1 = __float_as_uint(W2s[kt * 8 + t4 + 4][nt * 8 + g]);
                    mma8(c2[nt], a0, a1, a2, a3, b0, b1);
                }
            }
        }
    }

    // epilogue: add bias, tf32-round (q additionally pre-scaled by 0.125)
    const int r0 = m0 + w * 16 + g;
    const float* bias1 = fused ? bk : bq;
    float* out1        = fused ? g_k : g_q;
    const float sc     = fused ? 1.0f : 0.125f;
#pragma unroll
    for (int nt = 0; nt < 8; ++nt) {
        int cc = nt * 8 + 2 * t4;
        float b0 = bias1[cc], b1 = bias1[cc + 1];
        *(float2*)(out1 + (size_t)r0 * DK + cc) =
            make_float2(f2tff((c1[nt][0] + b0) * sc), f2tff((c1[nt][1] + b1) * sc));
        *(float2*)(out1 + (size_t)(r0 + 8) * DK + cc) =
            make_float2(f2tff((c1[nt][2] + b0) * sc), f2tff((c1[nt][3] + b1) * sc));
    }
    if (fused) {
#pragma unroll
        for (int nt = 0; nt < 8; ++nt) {
            int cc = nt * 8 + 2 * t4;
            float b0 = bv[cc], b1 = bv[cc + 1];
            *(float2*)(g_v + (size_t)r0 * DK + cc) =
                make_float2(f2tff(c2[nt][0] + b0), f2tff(c2[nt][1] + b1));
            *(float2*)(g_v + (size_t)(r0 + 8) * DK + cc) =
                make_float2(f2tff(c2[nt][2] + b0), f2tff(c2[nt][3] + b1));
        }
    }
}

// ---------------------------------------------------------------------------
// Kernel 3: causal flash attention (one head) on tf32 tensor cores.
// Block = 64 q-rows, 256 threads = 8 warps.
// warp w: band = w>>1 (16-row band, 0..3), ch = w&1 (32-key / 32-dim half).
// K/V arrive pre-rounded; P reuses the K smem buffer after the S phase.
// ---------------------------------------------------------------------------
__global__ void __launch_bounds__(256) attn_kernel() {
    const int b  = blockIdx.x & 3;
    const int it = (NQT2 - 1) - (blockIdx.x >> 2);   // longest-first

    __shared__ float kk[64][68];     // K tile [key][dim] -> P tile [row][key]
    __shared__ float vv[64][72];     // V tile [key][dim]
    __shared__ float redm[2][64];
    __shared__ float redl[2][64];

    const int t    = threadIdx.x;
    const int w    = t >> 5;
    const int lane = t & 31;
    const int band = w >> 1;       // 0..3
    const int ch   = w & 1;        // 0..1
    const int g    = lane >> 2;    // 0..7
    const int t4   = lane & 3;     // 0..3
    const int r0   = band * 16 + g;   // q-row within tile (and +8)

    // ---- stage Q tile (64x64, already scaled+rounded) into kk ----
    const float* qg = g_q + (size_t)(b * SS + it * QT2) * DK;
#pragma unroll
    for (int u = 0; u < 4; ++u) {
        int fi = t + u * 256;        // 1024 float4
        int r  = fi >> 4;
        int c4 = (fi & 15) << 2;
        *(float4*)&kk[r][c4] = *(const float4*)(qg + r * DK + c4);
    }
    __syncthreads();

    // resident Q A-fragments
    unsigned aq[8][4];
#pragma unroll
    for (int kt = 0; kt < 8; ++kt) {
        aq[kt][0] = __float_as_uint(kk[r0    ][kt * 8 + t4    ]);
        aq[kt][1] = __float_as_uint(kk[r0 + 8][kt * 8 + t4    ]);
        aq[kt][2] = __float_as_uint(kk[r0    ][kt * 8 + t4 + 4]);
        aq[kt][3] = __float_as_uint(kk[r0 + 8][kt * 8 + t4 + 4]);
    }

    float o[4][4] = {};
    float mrow0 = -1e30f, mrow1 = -1e30f;
    float lrow0 = 0.f,    lrow1 = 0.f;

    const int ntiles = it + 1;
    const float* kgp = g_k + (size_t)(b * SS) * DK;
    const float* vgp = g_v + (size_t)(b * SS) * DK;
    const int qpos0 = it * QT2 + r0;

    for (int jt = 0; jt < ntiles; ++jt) {
        __syncthreads();   // prior iter's P/V readers (and Q fragment reads) done
        // ---- load K,V tiles (64x64 each, pre-rounded): 4 float4 each/thread ----
#pragma unroll
        for (int u = 0; u < 4; ++u) {
            int fi = t + u * 256;
            int r  = fi >> 4;
            int c4 = (fi & 15) << 2;
            *(float4*)&kk[r][c4] = *(const float4*)(kgp + (size_t)(jt * 64 + r) * DK + c4);
            *(float4*)&vv[r][c4] = *(const float4*)(vgp + (size_t)(jt * 64 + r) * DK + c4);
        }
        __syncthreads();

        // ---- S = Q K^T (warp: 16 rows x 32 keys) ----
        float c[4][4] = {};
#pragma unroll
        for (int kt = 0; kt < 8; ++kt) {
#pragma unroll
            for (int nt = 0; nt < 4; ++nt) {
                unsigned b0 = __float_as_uint(kk[ch * 32 + nt * 8 + g][kt * 8 + t4    ]);
                unsigned b1 = __float_as_uint(kk[ch * 32 + nt * 8 + g][kt * 8 + t4 + 4]);
                mma8(c[nt], aq[kt][0], aq[kt][1], aq[kt][2], aq[kt][3], b0, b1);
            }
        }

        // ---- causal mask (only diagonal tile) ----
        if (jt == ntiles - 1) {
#pragma unroll
            for (int nt = 0; nt < 4; ++nt) {
                int kp = jt * 64 + ch * 32 + nt * 8 + 2 * t4;
                if (kp     > qpos0)     c[nt][0] = -1e30f;
                if (kp + 1 > qpos0)     c[nt][1] = -1e30f;
                if (kp     > qpos0 + 8) c[nt][2] = -1e30f;
                if (kp + 1 > qpos0 + 8) c[nt][3] = -1e30f;
            }
        }

        // ---- local row max (quad reduce) ----
        float rm0 = -1e30f, rm1 = -1e30f;
#pragma unroll
        for (int nt = 0; nt < 4; ++nt) {
            rm0 = fmaxf(rm0, fmaxf(c[nt][0], c[nt][1]));
            rm1 = fmaxf(rm1, fmaxf(c[nt][2], c[nt][3]));
        }
        rm0 = fmaxf(rm0, __shfl_xor_sync(0xffffffffu, rm0, 1));
        rm0 = fmaxf(rm0, __shfl_xor_sync(0xffffffffu, rm0, 2));
        rm1 = fmaxf(rm1, __shfl_xor_sync(0xffffffffu, rm1, 1));
        rm1 = fmaxf(rm1, __shfl_xor_sync(0xffffffffu, rm1, 2));
        if (t4 == 0) {
            redm[ch][r0]     = rm0;
            redm[ch][r0 + 8] = rm1;
        }
        __syncthreads();   // redm ready; also: all warps done reading kk (S phase)

        float nm0 = fmaxf(mrow0, fmaxf(redm[0][r0],     redm[1][r0]));
        float nm1 = fmaxf(mrow1, fmaxf(redm[0][r0 + 8], redm[1][r0 + 8]));
        float corr0 = __expf(mrow0 - nm0); mrow0 = nm0;
        float corr1 = __expf(mrow1 - nm1); mrow1 = nm1;

        float rs0 = 0.f, rs1 = 0.f;
#pragma unroll
        for (int nt = 0; nt < 4; ++nt) {
            c[nt][0] = __expf(c[nt][0] - nm0);
            c[nt][1] = __expf(c[nt][1] - nm0);
            c[nt][2] = __expf(c[nt][2] - nm1);
            c[nt][3] = __expf(c[nt][3] - nm1);
            rs0 += c[nt][0] + c[nt][1];
            rs1 += c[nt][2] + c[nt][3];
        }
        rs0 += __shfl_xor_sync(0xffffffffu, rs0, 1);
        rs0 += __shfl_xor_sync(0xffffffffu, rs0, 2);
        rs1 += __shfl_xor_sync(0xffffffffu, rs1, 1);
        rs1 += __shfl_xor_sync(0xffffffffu, rs1, 2);
        if (t4 == 0) {
            redl[ch][r0]     = rs0;
            redl[ch][r0 + 8] = rs1;
        }
        // store P (tf32-rounded) into kk region: [row][key]
#pragma unroll
        for (int nt = 0; nt < 4; ++nt) {
            int kc = ch * 32 + nt * 8 + 2 * t4;
            *(float2*)&kk[r0][kc]     = make_float2(f2tff(c[nt][0]), f2tff(c[nt][1]));
            *(float2*)&kk[r0 + 8][kc] = make_float2(f2tff(c[nt][2]), f2tff(c[nt][3]));
        }
        // rescale O accumulators
#pragma unroll
        for (int nt = 0; nt < 4; ++nt) {
            o[nt][0] *= corr0; o[nt][1] *= corr0;
            o[nt][2] *= corr1; o[nt][3] *= corr1;
        }
        __syncthreads();   // P + redl visible
        lrow0 = lrow0 * corr0 + redl[0][r0]     + redl[1][r0];
        lrow1 = lrow1 * corr1 + redl[0][r0 + 8] + redl[1][r0 + 8];

        // ---- O += P V (warp: 16 rows x 32 dims) ----
#pragma unroll
        for (int kt = 0; kt < 8; ++kt) {
            unsigned a0 = __float_as_uint(kk[r0    ][kt * 8 + t4    ]);
            unsigned a1 = __float_as_uint(kk[r0 + 8][kt * 8 + t4    ]);
            unsigned a2 = __float_as_uint(kk[r0    ][kt * 8 + t4 + 4]);
            unsigned a3 = __float_as_uint(kk[r0 + 8][kt * 8 + t4 + 4]);
#pragma unroll
            for (int nt = 0; nt < 4; ++nt) {
                unsigned b0 = __float_as_uint(vv[kt * 8 + t4    ][ch * 32 + nt * 8 + g]);
                unsigned b1 = __float_as_uint(vv[kt * 8 + t4 + 4][ch * 32 + nt * 8 + g]);
                mma8(o[nt], a0, a1, a2, a3, b0, b1);
            }
        }
    }

    // ---- epilogue: o = acc / l, tf32-rounded for outgemm ----
    float inv0 = 1.f / lrow0;
    float inv1 = 1.f / lrow1;
    float* og = g_o + (size_t)(b * SS + it * QT2 + band * 16) * DV + ch * 32;
#pragma unroll
    for (int nt = 0; nt < 4; ++nt) {
        int dc = nt * 8 + 2 * t4;
        *(float2*)(og + (size_t)g * DV + dc) =
            make_float2(f2tff(o[nt][0] * inv0), f2tff(o[nt][1] * inv0));
        *(float2*)(og + (size_t)(g + 8) * DV + dc) =
            make_float2(f2tff(o[nt][2] * inv1), f2tff(o[nt][3] * inv1));
    }
}

// ---------------------------------------------------------------------------
// Kernel 4: out[8192,512] = o[8192,64] @ woeff[64,512] + bo  (tf32 mma)
// Inputs pre-rounded -> raw loads. 128 threads = 4 warps; 64x64 tile, K=64.
// ---------------------------------------------------------------------------
__global__ void __launch_bounds__(128) outgemm_mma_kernel(
    const float* __restrict__ bo, float* __restrict__ out)
{
    const int m0 = blockIdx.x * 64;
    const int n0 = blockIdx.y * 64;

    __shared__ float Ao[64][68];     // o tile [row][k], pitch 68 -> bank 4g+t4
    __shared__ float Ws[64][72];     // woeff tile [k][n], pitch 72 -> bank 8t4+g

    const int t    = threadIdx.x;
    const int w    = t >> 5;
    const int lane = t & 31;
    const int g    = lane >> 2;
    const int t4   = lane & 3;

#pragma unroll
    for (int u = 0; u < 8; ++u) {
        int fi = t + u * 128;
        int r  = fi >> 4;
        int c4 = (fi & 15) << 2;
        *(float4*)&Ao[r][c4] = *(const float4*)(g_o + (size_t)(m0 + r) * DV + c4);
        *(float4*)&Ws[r][c4] = *(const float4*)(g_woeff + (size_t)r * DD + n0 + c4);
    }
    __syncthreads();

    float c[8][4] = {};
#pragma unroll
    for (int kt = 0; kt < 8; ++kt) {
        unsigned a0 = __float_as_uint(Ao[w * 16 + g    ][kt * 8 + t4    ]);
        unsigned a1 = __float_as_uint(Ao[w * 16 + g + 8][kt * 8 + t4    ]);
        unsigned a2 = __float_as_uint(Ao[w * 16 + g    ][kt * 8 + t4 + 4]);
        unsigned a3 = __float_as_uint(Ao[w * 16 + g + 8][kt * 8 + t4 + 4]);
#pragma unroll
        for (int nt = 0; nt < 8; ++nt) {
            unsigned b0 = __float_as_uint(Ws[kt * 8 + t4    ][nt * 8 + g]);
            unsigned b1 = __float_as_uint(Ws[kt * 8 + t4 + 4][nt * 8 + g]);
            mma8(c[nt], a0, a1, a2, a3, b0, b1);
        }
    }

    const int row0 = m0 + w * 16 + g;
#pragma unroll
    for (int nt = 0; nt < 8; ++nt) {
        int cc = n0 + nt * 8 + 2 * t4;
        float b0 = bo[cc], b1 = bo[cc + 1];
        *(float2*)(out + (size_t)row0 * DD + cc)       = make_float2(c[nt][0] + b0, c[nt][1] + b1);
        *(float2*)(out + (size_t)(row0 + 8) * DD + cc) = make_float2(c[nt][2] + b0, c[nt][3] + b1);
    }
}

// ---------------------------------------------------------------------------
// Launch
// Inputs: 0 query, 1 key, 2 value(unused), 3 Wq, 4 bq, 5 Wk, 6 bk,
//         7 Wv, 8 bv, 9 Wo, 10 bo
// ---------------------------------------------------------------------------
extern "C" void kernel_launch(void* const* d_in, const int* in_sizes, int n_in,
                              void* d_out, int out_size)
{
    const float* query = (const float*)d_in[0];
    const float* key   = (const float*)d_in[1];
    const float* Wq    = (const float*)d_in[3];
    const float* bq    = (const float*)d_in[4];
    const float* Wk    = (const float*)d_in[5];
    const float* bk    = (const float*)d_in[6];
    const float* Wv    = (const float*)d_in[7];
    const float* bv    = (const float*)d_in[8];
    const float* Wo    = (const float*)d_in[9];
    const float* bo    = (const float*)d_in[10];
    float* out = (float*)d_out;

    woeff_kernel<<<64, 512>>>(Wo);
    proj_mma_kernel<<<dim3(BS / 64, 2), 128>>>(query, key, Wq, bq, Wk, bk, Wv, bv);
    attn_kernel<<<BB * NQT2, 256>>>();
    outgemm_mma_kernel<<<dim3(BS / 64, DD / 64), 128>>>(bo, out);
}